// round 2
// baseline (speedup 1.0000x reference)
#include <cuda_runtime.h>
#include <cstdint>
#include <math.h>

#define LSEQ 4096
#define BATCH 2
#define DIMC 256
#define EPS_F 1e-5f

// ---------------- scratch (device globals; no dynamic allocation) ----------------
__device__ float g_seq0n[BATCH*DIMC*LSEQ];
__device__ float g_seq1n[BATCH*DIMC*LSEQ];
__device__ float g_x   [BATCH*DIMC*LSEQ];
__device__ float g_z   [BATCH*DIMC*LSEQ];
__device__ float g_xc  [2][BATCH*DIMC*LSEQ];
__device__ float g_dbl [2][BATCH*32*LSEQ];
__device__ float g_dt  [2][BATCH*DIMC*LSEQ];
__device__ float g_P   [2][64*BATCH*DIMC*8];
__device__ float g_S   [2][64*BATCH*DIMC*8];
__device__ float g_Hi  [2][64*BATCH*DIMC*8];
__device__ float g_y   [2][BATCH*DIMC*LSEQ];
__device__ float g_yn  [3*BATCH*DIMC*LSEQ];
__device__ float g_o   [6*DIMC*LSEQ];

__device__ __forceinline__ float sigmoidf_(float x){ return 1.f/(1.f+__expf(-x)); }
__device__ __forceinline__ float softplusf_(float x){ return x>20.f ? x : log1pf(__expf(x)); }

// ---------------- layernorm over channel dim (strided, coalesced across tokens) ----------------
__global__ void ln_k(const float* __restrict__ in0, const float* __restrict__ in1,
                     const float* __restrict__ w0, const float* __restrict__ b0,
                     const float* __restrict__ w1, const float* __restrict__ b1,
                     float* __restrict__ o0, float* __restrict__ o1)
{
    const float* in = blockIdx.y ? in1 : in0;
    const float* w  = blockIdx.y ? w1  : w0;
    const float* bb = blockIdx.y ? b1  : b0;
    float* out      = blockIdx.y ? o1  : o0;
    int idx = blockIdx.x * blockDim.x + threadIdx.x;   // 0..8191 token
    int b = idx >> 12, l = idx & (LSEQ-1);
    const float* p = in + (size_t)b*DIMC*LSEQ + l;
    float s = 0.f, s2 = 0.f;
    #pragma unroll 8
    for (int c = 0; c < DIMC; c++) { float v = p[(size_t)c*LSEQ]; s += v; s2 += v*v; }
    float mean = s * (1.f/DIMC);
    float var  = s2 * (1.f/DIMC) - mean*mean;
    float rstd = rsqrtf(var + EPS_F);
    float* q = out + (size_t)b*DIMC*LSEQ + l;
    #pragma unroll 8
    for (int c = 0; c < DIMC; c++) {
        float v = p[(size_t)c*LSEQ];
        q[(size_t)c*LSEQ] = (v-mean)*rstd*w[c] + bb[c];
    }
}

// ---------------- depthwise causal conv (K=4) + silu; rev maps logical->physical time ----------------
__global__ void conv_silu_k(const float* __restrict__ x, const float* __restrict__ w,
                            const float* __restrict__ bias, float* __restrict__ xc, int rev)
{
    int t  = blockIdx.x * blockDim.x + threadIdx.x;  // logical time
    int bd = blockIdx.y;                             // b*256+d
    int d  = bd & 255;
    const float* xp = x + (size_t)bd*LSEQ;
    float acc = bias[d];
    #pragma unroll
    for (int k = 0; k < 4; k++) {
        int s = t - 3 + k;
        if (s >= 0) {
            int ph = rev ? (LSEQ-1-s) : s;
            acc += w[d*4+k] * xp[ph];
        }
    }
    xc[(size_t)bd*LSEQ + t] = acc * sigmoidf_(acc);
}

// ---------------- generic SGEMM, C[M,N] = A[M,K]*B[K,N], f32x2 packed FMA inner loop ----------------
enum { EP_NONE=0, EP_SPBIAS=1, EP_SKIP=2, EP_BIAS=3 };

template<int EP>
__global__ void __launch_bounds__(256) sgemm_k(
    const float* __restrict__ A, int lda, long long aStride,
    const float* __restrict__ B, int ldb, long long bStride,
    float* __restrict__ C, int ldc, long long cStride,
    int M, int Kdim,
    const float* __restrict__ bias,
    const float* __restrict__ skip, long long skipStride, int skipMod)
{
    __shared__ float As[8][128];
    __shared__ float Bs[8][128];
    int z = blockIdx.z;
    A += (size_t)z * aStride;
    B += (size_t)z * bStride;
    C += (size_t)z * cStride;
    size_t skipOff = 0;
    if (EP == EP_SKIP) skipOff = (size_t)(z % skipMod) * (size_t)skipStride;

    int m0 = blockIdx.y * 128;
    int n0 = blockIdx.x * 128;
    int tid = threadIdx.x;

    int ar  = tid >> 1;          // A tile row 0..127
    int ac  = (tid & 1) << 2;    // A tile k-col 0/4
    int brr = tid >> 5;          // B tile row 0..7
    int bc  = (tid & 31) << 2;   // B tile col *4

    int mt0 = (tid >> 4) << 2;   // 0..60
    int nt0 = (tid & 15) << 2;   // 0..60

    unsigned long long acc[8][4];
    #pragma unroll
    for (int i = 0; i < 8; i++)
        #pragma unroll
        for (int j = 0; j < 4; j++) acc[i][j] = 0ull;

    for (int k0 = 0; k0 < Kdim; k0 += 8) {
        float4 a4 = make_float4(0.f,0.f,0.f,0.f);
        int arow = m0 + ar;
        if (arow < M) a4 = *(const float4*)(A + (size_t)arow*lda + (k0 + ac));
        As[ac+0][ar] = a4.x; As[ac+1][ar] = a4.y; As[ac+2][ar] = a4.z; As[ac+3][ar] = a4.w;
        float4 b4 = *(const float4*)(B + (size_t)(k0 + brr)*ldb + (n0 + bc));
        *(float4*)&Bs[brr][bc] = b4;
        __syncthreads();
        #pragma unroll
        for (int kk = 0; kk < 8; kk++) {
            float4 aL = *(const float4*)&As[kk][mt0];
            float4 aH = *(const float4*)&As[kk][mt0+64];
            float av[8] = {aL.x,aL.y,aL.z,aL.w,aH.x,aH.y,aH.z,aH.w};
            unsigned long long b2[4];
            const unsigned long long* bpL = (const unsigned long long*)&Bs[kk][nt0];
            const unsigned long long* bpH = (const unsigned long long*)&Bs[kk][nt0+64];
            b2[0] = bpL[0]; b2[1] = bpL[1]; b2[2] = bpH[0]; b2[3] = bpH[1];
            #pragma unroll
            for (int i = 0; i < 8; i++) {
                unsigned long long a2;
                asm("mov.b64 %0, {%1, %1};" : "=l"(a2) : "f"(av[i]));
                #pragma unroll
                for (int j = 0; j < 4; j++) {
                    asm("fma.rn.f32x2 %0, %1, %2, %0;" : "+l"(acc[i][j]) : "l"(a2), "l"(b2[j]));
                }
            }
        }
        __syncthreads();
    }

    #pragma unroll
    for (int i = 0; i < 8; i++) {
        int m = m0 + ((i < 4) ? (mt0 + i) : (64 + mt0 + i - 4));
        if (m >= M) continue;
        float bv = 0.f;
        if (EP == EP_SPBIAS || EP == EP_BIAS) bv = bias[m];
        #pragma unroll
        for (int j = 0; j < 4; j++) {
            int n = n0 + ((j < 2) ? (nt0 + 2*j) : (64 + nt0 + 2*(j-2)));
            float2 v;
            asm("mov.b64 {%0, %1}, %2;" : "=f"(v.x), "=f"(v.y) : "l"(acc[i][j]));
            if (EP == EP_SPBIAS)      { v.x = softplusf_(v.x + bv); v.y = softplusf_(v.y + bv); }
            else if (EP == EP_BIAS)   { v.x += bv; v.y += bv; }
            else if (EP == EP_SKIP)   {
                const float* sp = skip + skipOff + (size_t)m*ldc + n;
                v.x += sp[0]; v.y += sp[1];
            }
            *(float2*)(C + (size_t)m*ldc + n) = v;
        }
    }
}

// ---------------- chunked selective scan ----------------
// pass A: per (b,d,n,chunk): P = prod dA over chunk, S = chunk-local final state (h0=0)
__global__ void __launch_bounds__(256) scanA_k(
    const float* __restrict__ dt, const float* __restrict__ xc,
    const float* __restrict__ dbl, const float* __restrict__ A_log,
    float* __restrict__ P, float* __restrict__ S)
{
    __shared__ float sdt[32][65], sx[32][65], sB[8][65];
    int chunk = blockIdx.x, b = blockIdx.y, d0 = blockIdx.z * 32;
    int tid = threadIdx.x;
    size_t base = ((size_t)(b*DIMC + d0))*LSEQ + chunk*64;
    for (int i = tid; i < 2048; i += 256) {
        int r = i >> 6, c = i & 63;
        sdt[r][c] = dt[base + (size_t)r*LSEQ + c];
        sx [r][c] = xc[base + (size_t)r*LSEQ + c];
    }
    size_t bbase = ((size_t)(b*32 + 16))*LSEQ + chunk*64;
    for (int i = tid; i < 512; i += 256) {
        int r = i >> 6, c = i & 63;
        sB[r][c] = dbl[bbase + (size_t)r*LSEQ + c];
    }
    __syncthreads();
    int dl = tid >> 3, n = tid & 7;
    float Aa = -__expf(A_log[(d0+dl)*8 + n]);
    float Pv = 1.f, Sv = 0.f;
    #pragma unroll 8
    for (int t = 0; t < 64; t++) {
        float dtv = sdt[dl][t];
        float dA  = __expf(dtv * Aa);
        Sv = Sv*dA + dtv * sx[dl][t] * sB[n][t];
        Pv *= dA;
    }
    size_t o = (((size_t)chunk*BATCH + b)*DIMC + d0+dl)*8 + n;
    P[o] = Pv; S[o] = Sv;
}

// pass B: sequential combine across 64 chunks; Hi[c] = state entering chunk c
__global__ void scanB_k(const float* __restrict__ P, const float* __restrict__ S,
                        float* __restrict__ Hi)
{
    int idx = blockIdx.x * blockDim.x + threadIdx.x;   // 0..4095 = (b,d,n)
    float h = 0.f;
    for (int c = 0; c < 64; c++) {
        size_t o = (size_t)c*4096 + idx;
        Hi[o] = h;
        h = h * P[o] + S[o];
    }
}

// pass C: replay chunk from Hi, emit y = (scan + x*D) * silu(z); rev handles final re-reversal
__global__ void __launch_bounds__(256) scanC_k(
    const float* __restrict__ dt, const float* __restrict__ xc,
    const float* __restrict__ dbl, const float* __restrict__ A_log,
    const float* __restrict__ Hi, const float* __restrict__ Dp,
    const float* __restrict__ z, float* __restrict__ y, int rev)
{
    __shared__ float sdt[32][65], sx[32][65], sB[8][65], sC[8][65];
    __shared__ float sy[32][64];
    int chunk = blockIdx.x, b = blockIdx.y, d0 = blockIdx.z * 32;
    int tid = threadIdx.x;
    size_t base = ((size_t)(b*DIMC + d0))*LSEQ + chunk*64;
    for (int i = tid; i < 2048; i += 256) {
        int r = i >> 6, c = i & 63;
        sdt[r][c] = dt[base + (size_t)r*LSEQ + c];
        sx [r][c] = xc[base + (size_t)r*LSEQ + c];
    }
    size_t bbase = ((size_t)(b*32 + 16))*LSEQ + chunk*64;
    size_t cbase = ((size_t)(b*32 + 24))*LSEQ + chunk*64;
    for (int i = tid; i < 512; i += 256) {
        int r = i >> 6, c = i & 63;
        sB[r][c] = dbl[bbase + (size_t)r*LSEQ + c];
        sC[r][c] = dbl[cbase + (size_t)r*LSEQ + c];
    }
    __syncthreads();
    int dl = tid >> 3, n = tid & 7;
    float Aa = -__expf(A_log[(d0+dl)*8 + n]);
    float h = Hi[(((size_t)chunk*BATCH + b)*DIMC + d0+dl)*8 + n];
    for (int t = 0; t < 64; t++) {
        float dtv = sdt[dl][t];
        float dA  = __expf(dtv * Aa);
        h = h*dA + dtv * sx[dl][t] * sB[n][t];
        float yv = h * sC[n][t];
        yv += __shfl_down_sync(0xffffffffu, yv, 4);
        yv += __shfl_down_sync(0xffffffffu, yv, 2);
        yv += __shfl_down_sync(0xffffffffu, yv, 1);
        if (n == 0) sy[dl][t] = yv;
    }
    __syncthreads();
    for (int i = tid; i < 2048; i += 256) {
        int r = i >> 6, c = i & 63;
        int tl = chunk*64 + c;
        int lp = rev ? (LSEQ-1-tl) : tl;
        size_t gi = ((size_t)(b*DIMC + d0 + r))*LSEQ + lp;
        float v = sy[r][c] + sx[r][c]*Dp[d0+r];
        float zz = z[gi];
        y[gi] = v * zz * sigmoidf_(zz);
    }
}

// ---------------- rmsnorm for the 3 heads (avg, fwd, bwd) ----------------
__global__ void rms3_k(const float* __restrict__ yf, const float* __restrict__ yb,
                       const float* __restrict__ w, float* __restrict__ yn)
{
    int idx = blockIdx.x * blockDim.x + threadIdx.x;  // token
    int b = idx >> 12, l = idx & (LSEQ-1);
    size_t base = (size_t)b*DIMC*LSEQ + l;
    float sa = 0.f, sf = 0.f, sb = 0.f;
    #pragma unroll 8
    for (int d = 0; d < DIMC; d++) {
        float vf = yf[base + (size_t)d*LSEQ];
        float vb = yb[base + (size_t)d*LSEQ];
        float va = 0.5f*(vf+vb);
        sa += va*va; sf += vf*vf; sb += vb*vb;
    }
    float ra = rsqrtf(sa*(1.f/DIMC) + EPS_F);
    float rf = rsqrtf(sf*(1.f/DIMC) + EPS_F);
    float rb = rsqrtf(sb*(1.f/DIMC) + EPS_F);
    const size_t HS = (size_t)BATCH*DIMC*LSEQ;
    #pragma unroll 8
    for (int d = 0; d < DIMC; d++) {
        float vf = yf[base + (size_t)d*LSEQ];
        float vb = yb[base + (size_t)d*LSEQ];
        float va = 0.5f*(vf+vb);
        float ww = w[d];
        size_t o = base + (size_t)d*LSEQ;
        yn[0*HS + o] = va*ra*ww;
        yn[1*HS + o] = vf*rf*ww;
        yn[2*HS + o] = vb*rb*ww;
    }
}

// ---------------- launch ----------------
extern "C" void kernel_launch(void* const* d_in, const int* in_sizes, int n_in,
                              void* d_out, int out_size)
{
    (void)in_sizes; (void)n_in; (void)out_size;
    const float* input0      = (const float*)d_in[0];
    const float* input1      = (const float*)d_in[1];
    const float* norm0_w     = (const float*)d_in[2];
    const float* norm0_b     = (const float*)d_in[3];
    const float* norm1_w     = (const float*)d_in[4];
    const float* norm1_b     = (const float*)d_in[5];
    const float* in_proj_w   = (const float*)d_in[6];
    const float* in_projz_w  = (const float*)d_in[7];
    const float* conv1d_w    = (const float*)d_in[8];
    const float* conv1d_bias = (const float*)d_in[9];
    const float* conv1db_w   = (const float*)d_in[10];
    const float* conv1db_bias= (const float*)d_in[11];
    const float* xproj_w     = (const float*)d_in[12];
    const float* xprojb_w    = (const float*)d_in[13];
    const float* dtproj_w    = (const float*)d_in[14];
    const float* dtproj_bias = (const float*)d_in[15];
    const float* dtprojb_w   = (const float*)d_in[16];
    const float* dtprojb_bias= (const float*)d_in[17];
    const float* A_log       = (const float*)d_in[18];
    const float* Ab_log      = (const float*)d_in[19];
    const float* D_p         = (const float*)d_in[20];
    const float* D_b         = (const float*)d_in[21];
    const float* rms_w       = (const float*)d_in[22];
    const float* out_proj_w  = (const float*)d_in[23];
    const float* conv3d_w    = (const float*)d_in[24];
    const float* conv3d_bias = (const float*)d_in[25];
    float* out = (float*)d_out;

    float *seq0n, *seq1n, *x_, *z_, *xc_, *dbl_, *dt_, *P_, *S_, *Hi_, *y_, *yn_, *o_;
    cudaGetSymbolAddress((void**)&seq0n, g_seq0n);
    cudaGetSymbolAddress((void**)&seq1n, g_seq1n);
    cudaGetSymbolAddress((void**)&x_,    g_x);
    cudaGetSymbolAddress((void**)&z_,    g_z);
    cudaGetSymbolAddress((void**)&xc_,   g_xc);
    cudaGetSymbolAddress((void**)&dbl_,  g_dbl);
    cudaGetSymbolAddress((void**)&dt_,   g_dt);
    cudaGetSymbolAddress((void**)&P_,    g_P);
    cudaGetSymbolAddress((void**)&S_,    g_S);
    cudaGetSymbolAddress((void**)&Hi_,   g_Hi);
    cudaGetSymbolAddress((void**)&y_,    g_y);
    cudaGetSymbolAddress((void**)&yn_,   g_yn);
    cudaGetSymbolAddress((void**)&o_,    g_o);

    const long long SB  = (long long)DIMC*LSEQ;      // 1M elements per (b) slab
    const long long SB32= (long long)32*LSEQ;
    const int SCN = 64*BATCH*DIMC*8;                 // P/S/Hi per-direction size

    // 1) layernorms (both tensors)
    ln_k<<<dim3(32,2), 256>>>(input0, input1, norm0_w, norm0_b, norm1_w, norm1_b, seq0n, seq1n);

    // 2) in_proj / in_projz
    sgemm_k<EP_NONE><<<dim3(32,2,2), 256>>>(in_proj_w, 256, 0, seq0n, LSEQ, SB,
                                            x_, LSEQ, SB, 256, 256, nullptr, nullptr, 0, 1);
    sgemm_k<EP_NONE><<<dim3(32,2,2), 256>>>(in_projz_w, 256, 0, seq1n, LSEQ, SB,
                                            z_, LSEQ, SB, 256, 256, nullptr, nullptr, 0, 1);

    for (int dir = 0; dir < 2; dir++) {
        float* xcD  = xc_  + (size_t)dir*BATCH*DIMC*LSEQ;
        float* dblD = dbl_ + (size_t)dir*BATCH*32*LSEQ;
        float* dtD  = dt_  + (size_t)dir*BATCH*DIMC*LSEQ;
        float* PD   = P_   + (size_t)dir*SCN;
        float* SD   = S_   + (size_t)dir*SCN;
        float* HiD  = Hi_  + (size_t)dir*SCN;
        float* yD   = y_   + (size_t)dir*BATCH*DIMC*LSEQ;
        const float* cw = dir ? conv1db_w    : conv1d_w;
        const float* cb = dir ? conv1db_bias : conv1d_bias;
        const float* xw = dir ? xprojb_w     : xproj_w;
        const float* dw = dir ? dtprojb_w    : dtproj_w;
        const float* db = dir ? dtprojb_bias : dtproj_bias;
        const float* al = dir ? Ab_log       : A_log;
        const float* Dd = dir ? D_b          : D_p;

        // 3) depthwise conv + silu
        conv_silu_k<<<dim3(16,512), 256>>>(x_, cw, cb, xcD, dir);
        // 4) xproj -> dbl (dt_raw | B | C)
        sgemm_k<EP_NONE><<<dim3(32,1,2), 256>>>(xw, 256, 0, xcD, LSEQ, SB,
                                                dblD, LSEQ, SB32, 32, 256, nullptr, nullptr, 0, 1);
        // 5) dtproj + softplus
        sgemm_k<EP_SPBIAS><<<dim3(32,2,2), 256>>>(dw, 16, 0, dblD, LSEQ, SB32,
                                                  dtD, LSEQ, SB, 256, 16, db, nullptr, 0, 1);
        // 6) chunked scan
        scanA_k<<<dim3(64,2,8), 256>>>(dtD, xcD, dblD, al, PD, SD);
        scanB_k<<<16, 256>>>(PD, SD, HiD);
        scanC_k<<<dim3(64,2,8), 256>>>(dtD, xcD, dblD, al, HiD, Dd, z_, yD, dir);
    }

    // 7) rmsnorm for 3 heads
    rms3_k<<<32, 256>>>(y_, y_ + (size_t)BATCH*DIMC*LSEQ, rms_w, yn_);

    // 8) out_proj (+skip) for 6 batches (head-major, then b)
    sgemm_k<EP_SKIP><<<dim3(32,2,6), 256>>>(out_proj_w, 256, 0, yn_, LSEQ, SB,
                                            o_, LSEQ, SB, 256, 256, nullptr,
                                            input0, SB, 2);
    // 9) conv3d (1200x256) + bias -> final output
    sgemm_k<EP_BIAS><<<dim3(32,10,6), 256>>>(conv3d_w, 256, 0, o_, LSEQ, SB,
                                             out, LSEQ, (long long)1200*LSEQ, 1200, 256,
                                             conv3d_bias, nullptr, 0, 1);
}